// round 13
// baseline (speedup 1.0000x reference)
#include <cuda_runtime.h>
#include <cuda_fp16.h>
#include <cstdint>

#define GRID_H 1024
#define GRID_W 1024
#define DIM_FEAT 32
#define HW (GRID_H * GRID_W)

// 64 MB table: params transposed to [H, W, C] fp16.
__device__ __half g_params_t[(size_t)DIM_FEAT * HW];

// ---------------------------------------------------------------------------
// Transpose [C, H*W] fp32 -> [H*W, C] fp16. Params read evict-first (stream).
// Table written WRITE-THROUGH: the L2 copy stays CLEAN, so when the sample
// kernel's 256MB output stream evicts table lines there is no dirty
// writeback (silent drop + cheap refill instead of write+read).
// ---------------------------------------------------------------------------
__global__ void transpose_kernel(const float* __restrict__ p,
                                 __half* __restrict__ pt) {
    __shared__ float tile[32][33];
    const int pix0 = blockIdx.x * 32;
    const int tx = threadIdx.x;
    const int ty = threadIdx.y;
    const int l = ty * 32 + tx;

#pragma unroll
    for (int i = 0; i < 32; i += 8) {
        tile[ty + i][tx] = __ldcs(&p[(size_t)(ty + i) * HW + pix0 + tx]);
    }
    __syncthreads();

    unsigned* ptv = (unsigned*)pt;
#pragma unroll
    for (int it = 0; it < 2; it++) {
        const int pix = it * 16 + (l >> 4);
        const int c2 = l & 15;
        const __half2 h = __floats2half2_rn(tile[2 * c2 + 0][pix],
                                            tile[2 * c2 + 1][pix]);
        const unsigned hv = *(const unsigned*)&h;
        unsigned* dst = ptv + (size_t)(pix0 + pix) * (DIM_FEAT / 2) + c2;
        asm volatile("st.global.wt.u32 [%0], %1;"
                     :: "l"(dst), "r"(hv) : "memory");
    }
}

// 256-bit streaming store: one instruction per lane's 8 fp32 channels.
__device__ __forceinline__ void stcs_v8(float* p, const float a[8]) {
    asm volatile(
        "st.global.cs.v8.b32 [%0], {%1,%2,%3,%4,%5,%6,%7,%8};"
        :: "l"(p),
           "f"(a[0]), "f"(a[1]), "f"(a[2]), "f"(a[3]),
           "f"(a[4]), "f"(a[5]), "f"(a[6]), "f"(a[7])
        : "memory");
}

// ---------------------------------------------------------------------------
// Bilinear sample: 4 lanes per point, each lane = 8 channels.
// 4 x 16B uint4 gathers (64B coalesced per corner across lanes);
// single 32B v8 streaming store per lane.
// ---------------------------------------------------------------------------
__global__ void sample_kernel(const float2* __restrict__ coord,
                              const __half* __restrict__ pt,
                              float* __restrict__ out, int n) {
    const int t = blockIdx.x * blockDim.x + threadIdx.x;
    const int pidx = t >> 2;     // point index
    const int q = t & 3;         // channel octet (8 channels)
    if (pidx >= n) return;

    const float2 xy = __ldcs(&coord[pidx]);

    // align_corners=True mapping
    const float ix = (xy.x + 1.0f) * 0.5f * (float)(GRID_W - 1);
    const float iy = (xy.y + 1.0f) * 0.5f * (float)(GRID_H - 1);

    const float ix0f = floorf(ix);
    const float iy0f = floorf(iy);
    const float fx = ix - ix0f;
    const float fy = iy - iy0f;

    const float w_nw = (1.0f - fx) * (1.0f - fy);
    const float w_ne = fx * (1.0f - fy);
    const float w_sw = (1.0f - fx) * fy;
    const float w_se = fx * fy;

    int ix0 = min(max((int)ix0f, 0), GRID_W - 1);
    int iy0 = min(max((int)iy0f, 0), GRID_H - 1);
    const int ix1 = min(ix0 + 1, GRID_W - 1);
    const int iy1 = min(iy0 + 1, GRID_H - 1);

    const size_t row0 = (size_t)iy0 * GRID_W;
    const size_t row1 = (size_t)iy1 * GRID_W;
    const int cq = 8 * q;
    const uint4 r_nw = *(const uint4*)(pt + (row0 + ix0) * DIM_FEAT + cq);
    const uint4 r_ne = *(const uint4*)(pt + (row0 + ix1) * DIM_FEAT + cq);
    const uint4 r_sw = *(const uint4*)(pt + (row1 + ix0) * DIM_FEAT + cq);
    const uint4 r_se = *(const uint4*)(pt + (row1 + ix1) * DIM_FEAT + cq);

    float acc[8];
#pragma unroll
    for (int i = 0; i < 8; i++) acc[i] = 0.0f;

    auto accum = [&](const uint4& r, float w) {
        const unsigned u[4] = {r.x, r.y, r.z, r.w};
#pragma unroll
        for (int j = 0; j < 4; j++) {
            const float2 v = __half22float2(*(const __half2*)&u[j]);
            acc[2 * j + 0] = fmaf(v.x, w, acc[2 * j + 0]);
            acc[2 * j + 1] = fmaf(v.y, w, acc[2 * j + 1]);
        }
    };
    accum(r_nw, w_nw);
    accum(r_ne, w_ne);
    accum(r_sw, w_sw);
    accum(r_se, w_se);

    stcs_v8(out + (size_t)pidx * DIM_FEAT + cq, acc);
}

extern "C" void kernel_launch(void* const* d_in, const int* in_sizes, int n_in,
                              void* d_out, int out_size) {
    const float2* coord = (const float2*)d_in[0];  // [N, 2]
    const float* params = (const float*)d_in[1];   // [1, 32, 1024, 1024]
    float* out = (float*)d_out;                    // [N, 32]
    const int n = in_sizes[0] / 2;

    __half* pt;
    cudaGetSymbolAddress((void**)&pt, g_params_t);

    dim3 tb(32, 8);
    transpose_kernel<<<HW / 32, tb>>>(params, pt);

    const int threads = 256;
    const long long total = (long long)n * 4;
    sample_kernel<<<(int)((total + threads - 1) / threads), threads>>>(
        coord, pt, out, n);
}

// round 14
// speedup vs baseline: 1.0005x; 1.0005x over previous
#include <cuda_runtime.h>
#include <cuda_fp16.h>
#include <cstdint>

#define GRID_H 1024
#define GRID_W 1024
#define DIM_FEAT 32
#define HW (GRID_H * GRID_W)

// 64 MB table: params transposed to [H, W, C] fp16.
__device__ __half g_params_t[(size_t)DIM_FEAT * HW];

// ---------------------------------------------------------------------------
// Transpose [C, H*W] fp32 -> [H*W, C] fp16. Params read evict-first (stream),
// table written write-through (measured neutral vs hinted; keeps L2 copy).
// ---------------------------------------------------------------------------
__global__ void transpose_kernel(const float* __restrict__ p,
                                 __half* __restrict__ pt) {
    __shared__ float tile[32][33];
    const int pix0 = blockIdx.x * 32;
    const int tx = threadIdx.x;
    const int ty = threadIdx.y;
    const int l = ty * 32 + tx;

#pragma unroll
    for (int i = 0; i < 32; i += 8) {
        tile[ty + i][tx] = __ldcs(&p[(size_t)(ty + i) * HW + pix0 + tx]);
    }
    __syncthreads();

    unsigned* ptv = (unsigned*)pt;
#pragma unroll
    for (int it = 0; it < 2; it++) {
        const int pix = it * 16 + (l >> 4);
        const int c2 = l & 15;
        const __half2 h = __floats2half2_rn(tile[2 * c2 + 0][pix],
                                            tile[2 * c2 + 1][pix]);
        const unsigned hv = *(const unsigned*)&h;
        unsigned* dst = ptv + (size_t)(pix0 + pix) * (DIM_FEAT / 2) + c2;
        asm volatile("st.global.wt.u32 [%0], %1;"
                     :: "l"(dst), "r"(hv) : "memory");
    }
}

// 256-bit WRITE-THROUGH store: output stream does not claim L2 lines,
// so it stops displacing the param table.
__device__ __forceinline__ void stwt_v8(float* p, const float a[8]) {
    asm volatile(
        "st.global.wt.v8.b32 [%0], {%1,%2,%3,%4,%5,%6,%7,%8};"
        :: "l"(p),
           "f"(a[0]), "f"(a[1]), "f"(a[2]), "f"(a[3]),
           "f"(a[4]), "f"(a[5]), "f"(a[6]), "f"(a[7])
        : "memory");
}

// ---------------------------------------------------------------------------
// Bilinear sample: 4 lanes per point, each lane = 8 channels.
// 4 x 16B uint4 gathers (64B coalesced per corner across lanes);
// single 32B v8 write-through store per lane. 32-bit element offsets.
// ---------------------------------------------------------------------------
__global__ void __launch_bounds__(256, 8)
sample_kernel(const float2* __restrict__ coord,
              const __half* __restrict__ pt,
              float* __restrict__ out, int n) {
    const int t = blockIdx.x * blockDim.x + threadIdx.x;
    const int pidx = t >> 2;     // point index
    const int q = t & 3;         // channel octet (8 channels)
    if (pidx >= n) return;

    const float2 xy = __ldcs(&coord[pidx]);

    // align_corners=True mapping
    const float ix = (xy.x + 1.0f) * 0.5f * (float)(GRID_W - 1);
    const float iy = (xy.y + 1.0f) * 0.5f * (float)(GRID_H - 1);

    const float ix0f = floorf(ix);
    const float iy0f = floorf(iy);
    const float fx = ix - ix0f;
    const float fy = iy - iy0f;

    const float w_nw = (1.0f - fx) * (1.0f - fy);
    const float w_ne = fx * (1.0f - fy);
    const float w_sw = (1.0f - fx) * fy;
    const float w_se = fx * fy;

    int ix0 = min(max((int)ix0f, 0), GRID_W - 1);
    int iy0 = min(max((int)iy0f, 0), GRID_H - 1);
    const int ix1 = min(ix0 + 1, GRID_W - 1);
    const int iy1 = min(iy0 + 1, GRID_H - 1);

    // 32-bit element offsets (max 33.5M < 2^31).
    const unsigned row0 = (unsigned)iy0 * GRID_W;
    const unsigned row1 = (unsigned)iy1 * GRID_W;
    const unsigned cq = 8u * (unsigned)q;
    const uint4 r_nw = *(const uint4*)(pt + (row0 + ix0) * DIM_FEAT + cq);
    const uint4 r_ne = *(const uint4*)(pt + (row0 + ix1) * DIM_FEAT + cq);
    const uint4 r_sw = *(const uint4*)(pt + (row1 + ix0) * DIM_FEAT + cq);
    const uint4 r_se = *(const uint4*)(pt + (row1 + ix1) * DIM_FEAT + cq);

    float acc[8];
#pragma unroll
    for (int i = 0; i < 8; i++) acc[i] = 0.0f;

    auto accum = [&](const uint4& r, float w) {
        const unsigned u[4] = {r.x, r.y, r.z, r.w};
#pragma unroll
        for (int j = 0; j < 4; j++) {
            const float2 v = __half22float2(*(const __half2*)&u[j]);
            acc[2 * j + 0] = fmaf(v.x, w, acc[2 * j + 0]);
            acc[2 * j + 1] = fmaf(v.y, w, acc[2 * j + 1]);
        }
    };
    accum(r_nw, w_nw);
    accum(r_ne, w_ne);
    accum(r_sw, w_sw);
    accum(r_se, w_se);

    stwt_v8(out + (unsigned)pidx * DIM_FEAT + cq, acc);
}

extern "C" void kernel_launch(void* const* d_in, const int* in_sizes, int n_in,
                              void* d_out, int out_size) {
    const float2* coord = (const float2*)d_in[0];  // [N, 2]
    const float* params = (const float*)d_in[1];   // [1, 32, 1024, 1024]
    float* out = (float*)d_out;                    // [N, 32]
    const int n = in_sizes[0] / 2;

    __half* pt;
    cudaGetSymbolAddress((void**)&pt, g_params_t);

    dim3 tb(32, 8);
    transpose_kernel<<<HW / 32, tb>>>(params, pt);

    const int threads = 256;
    const long long total = (long long)n * 4;
    sample_kernel<<<(int)((total + threads - 1) / threads), threads>>>(
        coord, pt, out, n);
}

// round 15
// speedup vs baseline: 1.0647x; 1.0642x over previous
#include <cuda_runtime.h>
#include <cuda_fp16.h>
#include <cstdint>

#define GRID_H 1024
#define GRID_W 1024
#define DIM_FEAT 32
#define HW (GRID_H * GRID_W)

// 64 MB table: params transposed to [H, W, C] fp16.
__device__ __half g_params_t[(size_t)DIM_FEAT * HW];

// ---------------------------------------------------------------------------
// Transpose [C, H*W] fp32 -> [H*W, C] fp16.
// Tile: 32 channels x 64 pixels. float4 global reads (coalesced 128B),
// conflict-free smem, 16B v4.b32 writes (64B per pixel, 4 lanes/pixel).
// ---------------------------------------------------------------------------
__global__ void __launch_bounds__(256)
transpose_kernel(const float* __restrict__ p, __half* __restrict__ pt) {
    __shared__ float tile[32][65];  // 65 pad: conflict-free column reads
    const int pix0 = blockIdx.x * 64;
    const int t = threadIdx.x;      // 0..255

    // Read phase: thread covers float4 xq of channels c and c+16.
    {
        const int c = t >> 4;         // 0..15
        const int xq = t & 15;        // float4 index 0..15 (64 pixels)
        const float4 a = __ldcs((const float4*)(p + (size_t)c * HW + pix0) + xq);
        const float4 b = __ldcs((const float4*)(p + (size_t)(c + 16) * HW + pix0) + xq);
        tile[c][4 * xq + 0] = a.x;
        tile[c][4 * xq + 1] = a.y;
        tile[c][4 * xq + 2] = a.z;
        tile[c][4 * xq + 3] = a.w;
        tile[c + 16][4 * xq + 0] = b.x;
        tile[c + 16][4 * xq + 1] = b.y;
        tile[c + 16][4 * xq + 2] = b.z;
        tile[c + 16][4 * xq + 3] = b.w;
    }
    __syncthreads();

    // Write phase: thread covers 8 channels (cg) of one pixel -> one 16B store.
    {
        const int pix = t >> 2;       // 0..63
        const int cg = t & 3;         // channel group (8 channels)
        const int c0 = 8 * cg;
        uint4 v;
        unsigned* vp = (unsigned*)&v;
#pragma unroll
        for (int j = 0; j < 4; j++) {
            const __half2 h = __floats2half2_rn(tile[c0 + 2 * j][pix],
                                                tile[c0 + 2 * j + 1][pix]);
            vp[j] = *(const unsigned*)&h;
        }
        *(uint4*)(pt + (size_t)(pix0 + pix) * DIM_FEAT + c0) = v;
    }
}

// 256-bit streaming store: one instruction per lane's 8 fp32 channels.
__device__ __forceinline__ void stcs_v8(float* p, const float a[8]) {
    asm volatile(
        "st.global.cs.v8.b32 [%0], {%1,%2,%3,%4,%5,%6,%7,%8};"
        :: "l"(p),
           "f"(a[0]), "f"(a[1]), "f"(a[2]), "f"(a[3]),
           "f"(a[4]), "f"(a[5]), "f"(a[6]), "f"(a[7])
        : "memory");
}

// ---------------------------------------------------------------------------
// Bilinear sample (best measured config, 80.4us): 4 lanes/point, lane = 8
// channels; 4 x 16B uint4 gathers (64B coalesced per corner); one 32B v8
// streaming store per lane; 32-bit element offsets.
// ---------------------------------------------------------------------------
__global__ void __launch_bounds__(256, 8)
sample_kernel(const float2* __restrict__ coord,
              const __half* __restrict__ pt,
              float* __restrict__ out, int n) {
    const int t = blockIdx.x * blockDim.x + threadIdx.x;
    const int pidx = t >> 2;     // point index
    const int q = t & 3;         // channel octet (8 channels)
    if (pidx >= n) return;

    const float2 xy = __ldcs(&coord[pidx]);

    // align_corners=True mapping
    const float ix = (xy.x + 1.0f) * 0.5f * (float)(GRID_W - 1);
    const float iy = (xy.y + 1.0f) * 0.5f * (float)(GRID_H - 1);

    const float ix0f = floorf(ix);
    const float iy0f = floorf(iy);
    const float fx = ix - ix0f;
    const float fy = iy - iy0f;

    const float w_nw = (1.0f - fx) * (1.0f - fy);
    const float w_ne = fx * (1.0f - fy);
    const float w_sw = (1.0f - fx) * fy;
    const float w_se = fx * fy;

    int ix0 = min(max((int)ix0f, 0), GRID_W - 1);
    int iy0 = min(max((int)iy0f, 0), GRID_H - 1);
    const int ix1 = min(ix0 + 1, GRID_W - 1);
    const int iy1 = min(iy0 + 1, GRID_H - 1);

    const unsigned row0 = (unsigned)iy0 * GRID_W;
    const unsigned row1 = (unsigned)iy1 * GRID_W;
    const unsigned cq = 8u * (unsigned)q;
    const uint4 r_nw = *(const uint4*)(pt + (row0 + ix0) * DIM_FEAT + cq);
    const uint4 r_ne = *(const uint4*)(pt + (row0 + ix1) * DIM_FEAT + cq);
    const uint4 r_sw = *(const uint4*)(pt + (row1 + ix0) * DIM_FEAT + cq);
    const uint4 r_se = *(const uint4*)(pt + (row1 + ix1) * DIM_FEAT + cq);

    float acc[8];
#pragma unroll
    for (int i = 0; i < 8; i++) acc[i] = 0.0f;

    auto accum = [&](const uint4& r, float w) {
        const unsigned u[4] = {r.x, r.y, r.z, r.w};
#pragma unroll
        for (int j = 0; j < 4; j++) {
            const float2 v = __half22float2(*(const __half2*)&u[j]);
            acc[2 * j + 0] = fmaf(v.x, w, acc[2 * j + 0]);
            acc[2 * j + 1] = fmaf(v.y, w, acc[2 * j + 1]);
        }
    };
    accum(r_nw, w_nw);
    accum(r_ne, w_ne);
    accum(r_sw, w_sw);
    accum(r_se, w_se);

    stcs_v8(out + (unsigned)pidx * DIM_FEAT + cq, acc);
}

extern "C" void kernel_launch(void* const* d_in, const int* in_sizes, int n_in,
                              void* d_out, int out_size) {
    const float2* coord = (const float2*)d_in[0];  // [N, 2]
    const float* params = (const float*)d_in[1];   // [1, 32, 1024, 1024]
    float* out = (float*)d_out;                    // [N, 32]
    const int n = in_sizes[0] / 2;

    __half* pt;
    cudaGetSymbolAddress((void**)&pt, g_params_t);

    transpose_kernel<<<HW / 64, 256>>>(params, pt);

    const int threads = 256;
    const long long total = (long long)n * 4;
    sample_kernel<<<(int)((total + threads - 1) / threads), threads>>>(
        coord, pt, out, n);
}